// round 2
// baseline (speedup 1.0000x reference)
#include <cuda_runtime.h>
#include <cuda_bf16.h>
#include <stdint.h>

#define N_NODES_MAX 100000
#define N_EDGES_MAX 1600000
#define C_IN  128
#define C_HID 128
#define C_OUT 64

// Scratch (device globals; no allocation allowed)
__device__ float g_H1[N_NODES_MAX * C_HID];     // x @ W1
__device__ float g_A1[N_NODES_MAX * C_HID];     // aggregated layer1 (pre-bias/relu)
__device__ float g_H2[N_NODES_MAX * C_OUT];     // relu(A1+b1) @ W2
__device__ float g_dis[N_NODES_MAX];            // rsqrt(deg)
__device__ int   g_cnt[N_NODES_MAX];            // in-degree (excl. self-loop)
__device__ int   g_off[N_NODES_MAX + 1];        // CSR offsets
__device__ int   g_cur[N_NODES_MAX];            // placement cursors
__device__ int   g_src[N_EDGES_MAX];
__device__ int   g_dst[N_EDGES_MAX];
__device__ int   g_es[N_EDGES_MAX];             // CSR: src per slot
__device__ float g_en[N_EDGES_MAX];             // CSR: norm per slot
__device__ int   g_is64;

// ---------------------------------------------------------------------------
// dtype detection: int64 node ids < 2^31 have zero high words
__global__ void k_detect(const int* __restrict__ ei32) {
    int lane = threadIdx.x;
    int v = ei32[2 * lane + 1];
    unsigned b = __ballot_sync(0xFFFFFFFFu, v != 0);
    if (lane == 0) g_is64 = (b == 0) ? 1 : 0;
}

__global__ void k_zero(int n) {
    int i = blockIdx.x * blockDim.x + threadIdx.x;
    if (i < n) g_cnt[i] = 0;
}

// Canonicalize edges to int32 + count in-degrees (dst side)
__global__ void k_count(const void* __restrict__ ei, int E) {
    int e = blockIdx.x * blockDim.x + threadIdx.x;
    if (e >= E) return;
    int s, d;
    if (g_is64) {
        const long long* p = (const long long*)ei;
        s = (int)p[e]; d = (int)p[E + e];
    } else {
        const int* p = (const int*)ei;
        s = p[e]; d = p[E + e];
    }
    g_src[e] = s;
    g_dst[e] = d;
    atomicAdd(&g_cnt[d], 1);
}

// Single-block exclusive scan over g_cnt -> g_off; also dis=rsqrt(cnt+1), cur=0
__global__ void __launch_bounds__(1024) k_scan(int n, int E) {
    __shared__ int ssum[1024];
    int t = threadIdx.x;
    const int C = (n + 1023) / 1024;
    int lo = t * C;
    int hi = lo + C; if (hi > n) hi = n;
    int s = 0;
    for (int i = lo; i < hi; i++) s += g_cnt[i];
    ssum[t] = s;
    __syncthreads();
    #pragma unroll
    for (int off = 1; off < 1024; off <<= 1) {
        int u = (t >= off) ? ssum[t - off] : 0;
        __syncthreads();
        ssum[t] += u;
        __syncthreads();
    }
    int run = ssum[t] - s;  // exclusive prefix for this thread's chunk
    for (int i = lo; i < hi; i++) {
        int c = g_cnt[i];
        g_off[i] = run;
        run += c;
        g_cur[i] = 0;
        g_dis[i] = rsqrtf((float)c + 1.0f);
    }
    if (t == 1023) g_off[n] = ssum[1023];
}

// Place edges into CSR slots (grouped by dst); precompute norm
__global__ void k_place(int E) {
    int e = blockIdx.x * blockDim.x + threadIdx.x;
    if (e >= E) return;
    int s = g_src[e], d = g_dst[e];
    int pos = g_off[d] + atomicAdd(&g_cur[d], 1);
    g_es[pos] = s;
    g_en[pos] = g_dis[s] * g_dis[d];
}

// ---------------------------------------------------------------------------
// GEMM1: H1 = x @ W1
// Block: 256 thr (8 warps), 32 rows/block, 4 rows/warp, lane owns cols 4l..4l+3
__global__ void __launch_bounds__(256) k_gemm1(
    const float* __restrict__ x, const float* __restrict__ W, int n)
{
    extern __shared__ float sm[];
    float4* Ws4 = (float4*)sm;                    // [128][32] float4 = 64KB
    float*  Xs  = sm + C_IN * C_HID;              // [32][128] = 16KB

    int tid = threadIdx.x;
    const float4* Wg = (const float4*)W;
    #pragma unroll
    for (int i = tid; i < (C_IN * C_HID) / 4; i += 256) Ws4[i] = Wg[i];

    int rowBase = blockIdx.x * 32;
    float4* Xs4 = (float4*)Xs;
    for (int i = tid; i < 32 * (C_IN / 4); i += 256) {
        int r = i >> 5, c = i & 31;
        int gr = rowBase + r;
        Xs4[i] = (gr < n) ? ((const float4*)x)[(size_t)gr * 32 + c]
                          : make_float4(0.f, 0.f, 0.f, 0.f);
    }
    __syncthreads();

    int warp = tid >> 5, lane = tid & 31;
    int r0 = warp * 4;
    float4 acc0 = {0,0,0,0}, acc1 = {0,0,0,0}, acc2 = {0,0,0,0}, acc3 = {0,0,0,0};

    #pragma unroll 4
    for (int k = 0; k < C_IN; k++) {
        float4 w = Ws4[k * 32 + lane];
        float x0 = Xs[(r0 + 0) * C_IN + k];
        float x1 = Xs[(r0 + 1) * C_IN + k];
        float x2 = Xs[(r0 + 2) * C_IN + k];
        float x3 = Xs[(r0 + 3) * C_IN + k];
        acc0.x += x0 * w.x; acc0.y += x0 * w.y; acc0.z += x0 * w.z; acc0.w += x0 * w.w;
        acc1.x += x1 * w.x; acc1.y += x1 * w.y; acc1.z += x1 * w.z; acc1.w += x1 * w.w;
        acc2.x += x2 * w.x; acc2.y += x2 * w.y; acc2.z += x2 * w.z; acc2.w += x2 * w.w;
        acc3.x += x3 * w.x; acc3.y += x3 * w.y; acc3.z += x3 * w.z; acc3.w += x3 * w.w;
    }

    float4 accs[4] = {acc0, acc1, acc2, acc3};
    #pragma unroll
    for (int r = 0; r < 4; r++) {
        int gr = rowBase + r0 + r;
        if (gr < n) ((float4*)g_H1)[(size_t)gr * 32 + lane] = accs[r];
    }
}

// ---------------------------------------------------------------------------
// Aggregation layer1: one warp per dst node, CSR edges, no atomics.
// acc starts at self-loop term dis^2*H1[d].
__global__ void __launch_bounds__(256) k_agg1(int n) {
    int w = (blockIdx.x * blockDim.x + threadIdx.x) >> 5;
    int lane = threadIdx.x & 31;
    if (w >= n) return;
    int d = w;
    float di = g_dis[d];
    float d2 = di * di;
    float4 acc = ((const float4*)g_H1)[(size_t)d * 32 + lane];
    acc.x *= d2; acc.y *= d2; acc.z *= d2; acc.w *= d2;

    int i = g_off[d], end = g_off[d + 1];
    // 2x unrolled for MLP
    for (; i + 2 <= end; i += 2) {
        int s0 = g_es[i], s1 = g_es[i + 1];
        float n0 = g_en[i], n1 = g_en[i + 1];
        float4 h0 = ((const float4*)g_H1)[(size_t)s0 * 32 + lane];
        float4 h1 = ((const float4*)g_H1)[(size_t)s1 * 32 + lane];
        acc.x += n0 * h0.x + n1 * h1.x;
        acc.y += n0 * h0.y + n1 * h1.y;
        acc.z += n0 * h0.z + n1 * h1.z;
        acc.w += n0 * h0.w + n1 * h1.w;
    }
    if (i < end) {
        int s0 = g_es[i];
        float n0 = g_en[i];
        float4 h0 = ((const float4*)g_H1)[(size_t)s0 * 32 + lane];
        acc.x += n0 * h0.x; acc.y += n0 * h0.y;
        acc.z += n0 * h0.z; acc.w += n0 * h0.w;
    }
    ((float4*)g_A1)[(size_t)d * 32 + lane] = acc;
}

// ---------------------------------------------------------------------------
// GEMM2: z = relu(A1 + b1); H2 = z @ W2
__global__ void __launch_bounds__(256) k_gemm2(
    const float* __restrict__ W2, const float* __restrict__ b1, int n)
{
    extern __shared__ float sm[];
    float2* Ws2 = (float2*)sm;                    // [128][32] float2 = 32KB
    float*  Xs  = sm + C_HID * C_OUT;             // [32][128] = 16KB

    int tid = threadIdx.x;
    const float2* Wg = (const float2*)W2;
    #pragma unroll
    for (int i = tid; i < (C_HID * C_OUT) / 2; i += 256) Ws2[i] = Wg[i];

    int rowBase = blockIdx.x * 32;
    float4* Xs4 = (float4*)Xs;
    for (int i = tid; i < 32 * (C_HID / 4); i += 256) {
        int r = i >> 5, c = i & 31;
        int gr = rowBase + r;
        float4 v = make_float4(0.f, 0.f, 0.f, 0.f);
        if (gr < n) {
            v = ((const float4*)g_A1)[(size_t)gr * 32 + c];
            v.x = fmaxf(v.x + __ldg(&b1[c * 4 + 0]), 0.f);
            v.y = fmaxf(v.y + __ldg(&b1[c * 4 + 1]), 0.f);
            v.z = fmaxf(v.z + __ldg(&b1[c * 4 + 2]), 0.f);
            v.w = fmaxf(v.w + __ldg(&b1[c * 4 + 3]), 0.f);
        }
        Xs4[i] = v;
    }
    __syncthreads();

    int warp = tid >> 5, lane = tid & 31;
    int r0 = warp * 4;
    float2 acc0 = {0,0}, acc1 = {0,0}, acc2 = {0,0}, acc3 = {0,0};

    #pragma unroll 4
    for (int k = 0; k < C_HID; k++) {
        float2 w = Ws2[k * 32 + lane];
        float x0 = Xs[(r0 + 0) * C_HID + k];
        float x1 = Xs[(r0 + 1) * C_HID + k];
        float x2 = Xs[(r0 + 2) * C_HID + k];
        float x3 = Xs[(r0 + 3) * C_HID + k];
        acc0.x += x0 * w.x; acc0.y += x0 * w.y;
        acc1.x += x1 * w.x; acc1.y += x1 * w.y;
        acc2.x += x2 * w.x; acc2.y += x2 * w.y;
        acc3.x += x3 * w.x; acc3.y += x3 * w.y;
    }

    float2 accs[4] = {acc0, acc1, acc2, acc3};
    #pragma unroll
    for (int r = 0; r < 4; r++) {
        int gr = rowBase + r0 + r;
        if (gr < n) ((float2*)g_H2)[(size_t)gr * 32 + lane] = accs[r];
    }
}

// ---------------------------------------------------------------------------
// Aggregation layer2: half-warp per dst node (64 cols = 16 lanes x float4).
// out = sum + dis^2*H2[d] + b2
__global__ void __launch_bounds__(256) k_agg2(
    const float* __restrict__ b2, float* __restrict__ out, int n)
{
    int hw = (blockIdx.x * blockDim.x + threadIdx.x) >> 4;
    int l16 = threadIdx.x & 15;
    if (hw >= n) return;
    int d = hw;
    float di = g_dis[d];
    float d2 = di * di;
    float4 acc = ((const float4*)g_H2)[(size_t)d * 16 + l16];
    acc.x *= d2; acc.y *= d2; acc.z *= d2; acc.w *= d2;

    int i = g_off[d], end = g_off[d + 1];
    for (; i + 2 <= end; i += 2) {
        int s0 = g_es[i], s1 = g_es[i + 1];
        float n0 = g_en[i], n1 = g_en[i + 1];
        float4 h0 = ((const float4*)g_H2)[(size_t)s0 * 16 + l16];
        float4 h1 = ((const float4*)g_H2)[(size_t)s1 * 16 + l16];
        acc.x += n0 * h0.x + n1 * h1.x;
        acc.y += n0 * h0.y + n1 * h1.y;
        acc.z += n0 * h0.z + n1 * h1.z;
        acc.w += n0 * h0.w + n1 * h1.w;
    }
    if (i < end) {
        int s0 = g_es[i];
        float n0 = g_en[i];
        float4 h0 = ((const float4*)g_H2)[(size_t)s0 * 16 + l16];
        acc.x += n0 * h0.x; acc.y += n0 * h0.y;
        acc.z += n0 * h0.z; acc.w += n0 * h0.w;
    }
    float4 bb = ((const float4*)b2)[l16];
    acc.x += bb.x; acc.y += bb.y; acc.z += bb.z; acc.w += bb.w;
    ((float4*)out)[(size_t)d * 16 + l16] = acc;
}

// ---------------------------------------------------------------------------
extern "C" void kernel_launch(void* const* d_in, const int* in_sizes, int n_in,
                              void* d_out, int out_size) {
    const float* x  = (const float*)d_in[0];
    const void*  ei = d_in[1];
    const float* W1 = (const float*)d_in[2];
    const float* b1 = (const float*)d_in[3];
    const float* W2 = (const float*)d_in[4];
    const float* b2 = (const float*)d_in[5];
    float* out = (float*)d_out;

    int n = in_sizes[0] / C_IN;        // 100000
    int E = in_sizes[1] / 2;           // 1600000

    cudaFuncSetAttribute(k_gemm1, cudaFuncAttributeMaxDynamicSharedMemorySize,
                         (C_IN * C_HID + 32 * C_IN) * sizeof(float));
    cudaFuncSetAttribute(k_gemm2, cudaFuncAttributeMaxDynamicSharedMemorySize,
                         (C_HID * C_OUT + 32 * C_HID) * sizeof(float));

    int nb_nodes = (n + 255) / 256;
    int nb_edges = (E + 255) / 256;

    k_detect<<<1, 32>>>((const int*)ei);
    k_zero<<<nb_nodes, 256>>>(n);
    k_count<<<nb_edges, 256>>>(ei, E);
    k_scan<<<1, 1024>>>(n, E);
    k_place<<<nb_edges, 256>>>(E);

    int gemm_blocks = (n + 31) / 32;
    size_t smem1 = (size_t)(C_IN * C_HID + 32 * C_IN) * sizeof(float);   // 80KB
    size_t smem2 = (size_t)(C_HID * C_OUT + 32 * C_HID) * sizeof(float); // 48KB

    k_gemm1<<<gemm_blocks, 256, smem1>>>(x, W1, n);

    long long t1 = (long long)n * 32;
    k_agg1<<<(int)((t1 + 255) / 256), 256>>>(n);

    k_gemm2<<<gemm_blocks, 256, smem2>>>(W2, b1, n);

    long long t2 = (long long)n * 16;
    k_agg2<<<(int)((t2 + 255) / 256), 256>>>(b2, out, n);
}

// round 13
// speedup vs baseline: 1.6317x; 1.6317x over previous
#include <cuda_runtime.h>
#include <cuda_bf16.h>
#include <stdint.h>

#define N_NODES_MAX 100000
#define N_EDGES_MAX 1600000
#define C_IN  128
#define C_HID 128
#define C_OUT 64
#define SCAN_BLK 256
#define MAX_SCAN_BLOCKS ((N_NODES_MAX + SCAN_BLK - 1) / SCAN_BLK + 1)

// Scratch (device globals; no allocation allowed)
__device__ float g_H1[N_NODES_MAX * C_HID];     // x @ W1
__device__ float g_A1[N_NODES_MAX * C_HID];     // aggregated layer1 (pre-bias/relu)
__device__ float g_H2[N_NODES_MAX * C_OUT];     // relu(A1+b1) @ W2
__device__ float g_dis[N_NODES_MAX];            // rsqrt(deg)
__device__ int   g_cnt[N_NODES_MAX];            // in-degree (excl. self-loop)
__device__ int   g_off[N_NODES_MAX + 1];        // CSR offsets
__device__ int   g_cur[N_NODES_MAX];            // placement cursors
__device__ int   g_bsum[MAX_SCAN_BLOCKS];       // per-block sums for scan
__device__ int   g_src[N_EDGES_MAX];
__device__ int   g_dst[N_EDGES_MAX];
__device__ int   g_es[N_EDGES_MAX];             // CSR: src per slot
__device__ float g_en[N_EDGES_MAX];             // CSR: norm per slot
__device__ int   g_is64;

// ---------------------------------------------------------------------------
// dtype detection: int64 node ids < 2^31 have zero high words
__global__ void k_detect(const int* __restrict__ ei32) {
    int lane = threadIdx.x;
    int v = ei32[2 * lane + 1];
    unsigned b = __ballot_sync(0xFFFFFFFFu, v != 0);
    if (lane == 0) g_is64 = (b == 0) ? 1 : 0;
}

__global__ void k_zero(int n) {
    int i = blockIdx.x * blockDim.x + threadIdx.x;
    if (i < n) g_cnt[i] = 0;
}

// Canonicalize edges to int32 + count in-degrees (dst side)
__global__ void k_count(const void* __restrict__ ei, int E) {
    int e = blockIdx.x * blockDim.x + threadIdx.x;
    if (e >= E) return;
    int s, d;
    if (g_is64) {
        const long long* p = (const long long*)ei;
        s = (int)p[e]; d = (int)p[E + e];
    } else {
        const int* p = (const int*)ei;
        s = p[e]; d = p[E + e];
    }
    g_src[e] = s;
    g_dst[e] = d;
    atomicAdd(&g_cnt[d], 1);
}

// ---------------------------------------------------------------------------
// Parallel 3-pass exclusive scan over g_cnt -> g_off
// Pass 1: per-block sums
__global__ void __launch_bounds__(SCAN_BLK) k_scan1(int n) {
    __shared__ int wsum[SCAN_BLK / 32];
    int i = blockIdx.x * SCAN_BLK + threadIdx.x;
    int v = (i < n) ? g_cnt[i] : 0;
    int lane = threadIdx.x & 31, w = threadIdx.x >> 5;
    #pragma unroll
    for (int o = 16; o > 0; o >>= 1) v += __shfl_down_sync(0xFFFFFFFFu, v, o);
    if (lane == 0) wsum[w] = v;
    __syncthreads();
    if (w == 0) {
        int s = (lane < SCAN_BLK / 32) ? wsum[lane] : 0;
        #pragma unroll
        for (int o = 16; o > 0; o >>= 1) s += __shfl_down_sync(0xFFFFFFFFu, s, o);
        if (lane == 0) g_bsum[blockIdx.x] = s;
    }
}

// Pass 2: single block exclusive scan of block sums (nb <= 1024)
__global__ void __launch_bounds__(1024) k_scan2(int nb, int n) {
    __shared__ int wsum[32];
    int t = threadIdx.x;
    int v = (t < nb) ? g_bsum[t] : 0;
    int lane = t & 31, w = t >> 5;
    int inc = v;
    #pragma unroll
    for (int o = 1; o < 32; o <<= 1) {
        int u = __shfl_up_sync(0xFFFFFFFFu, inc, o);
        if (lane >= o) inc += u;
    }
    if (lane == 31) wsum[w] = inc;
    __syncthreads();
    if (w == 0) {
        int s = wsum[lane];                       // all 32 lanes active
        #pragma unroll
        for (int o = 1; o < 32; o <<= 1) {
            int u = __shfl_up_sync(0xFFFFFFFFu, s, o);
            if (lane >= o) s += u;
        }
        wsum[lane] = s;
    }
    __syncthreads();
    int excl = inc - v + (w > 0 ? wsum[w - 1] : 0);
    if (t < nb) g_bsum[t] = excl;
    if (t == nb - 1) g_off[n] = excl + v;   // total edge count
}

// Pass 3: per-block rescan + add block prefix; init cur and dis
// NOTE: warp-0 cross-warp scan keeps ALL 32 lanes in the shuffle (full mask),
// predicating only the value — the lane<8 guard around __shfl_up_sync was UB
// and the source of the nondeterministic hang.
__global__ void __launch_bounds__(SCAN_BLK) k_scan3(int n) {
    __shared__ int wsum[SCAN_BLK / 32];
    int i = blockIdx.x * SCAN_BLK + threadIdx.x;
    int v = (i < n) ? g_cnt[i] : 0;
    int lane = threadIdx.x & 31, w = threadIdx.x >> 5;
    int inc = v;
    #pragma unroll
    for (int o = 1; o < 32; o <<= 1) {
        int u = __shfl_up_sync(0xFFFFFFFFu, inc, o);
        if (lane >= o) inc += u;
    }
    if (lane == 31) wsum[w] = inc;
    __syncthreads();
    if (w == 0) {                                   // full warp active
        int s = (lane < SCAN_BLK / 32) ? wsum[lane] : 0;
        #pragma unroll
        for (int o = 1; o < 32; o <<= 1) {
            int u = __shfl_up_sync(0xFFFFFFFFu, s, o);
            if (lane >= o) s += u;
        }
        if (lane < SCAN_BLK / 32) wsum[lane] = s;
    }
    __syncthreads();
    int excl = inc - v + (w > 0 ? wsum[w - 1] : 0) + g_bsum[blockIdx.x];
    if (i < n) {
        g_off[i] = excl;
        g_cur[i] = 0;
        g_dis[i] = rsqrtf((float)v + 1.0f);
    }
}

// Place edges into CSR slots (grouped by dst); precompute norm
__global__ void k_place(int E) {
    int e = blockIdx.x * blockDim.x + threadIdx.x;
    if (e >= E) return;
    int s = g_src[e], d = g_dst[e];
    int pos = g_off[d] + atomicAdd(&g_cur[d], 1);
    g_es[pos] = s;
    g_en[pos] = g_dis[s] * g_dis[d];
}

// ---------------------------------------------------------------------------
// GEMM1: H1 = x @ W1
__global__ void __launch_bounds__(256) k_gemm1(
    const float* __restrict__ x, const float* __restrict__ W, int n)
{
    extern __shared__ float sm[];
    float4* Ws4 = (float4*)sm;                    // [128][32] float4 = 64KB
    float*  Xs  = sm + C_IN * C_HID;              // [32][128] = 16KB

    int tid = threadIdx.x;
    const float4* Wg = (const float4*)W;
    #pragma unroll
    for (int i = tid; i < (C_IN * C_HID) / 4; i += 256) Ws4[i] = Wg[i];

    int rowBase = blockIdx.x * 32;
    float4* Xs4 = (float4*)Xs;
    for (int i = tid; i < 32 * (C_IN / 4); i += 256) {
        int r = i >> 5, c = i & 31;
        int gr = rowBase + r;
        Xs4[i] = (gr < n) ? ((const float4*)x)[(size_t)gr * 32 + c]
                          : make_float4(0.f, 0.f, 0.f, 0.f);
    }
    __syncthreads();

    int warp = tid >> 5, lane = tid & 31;
    int r0 = warp * 4;
    float4 acc0 = {0,0,0,0}, acc1 = {0,0,0,0}, acc2 = {0,0,0,0}, acc3 = {0,0,0,0};

    #pragma unroll 4
    for (int k = 0; k < C_IN; k++) {
        float4 w = Ws4[k * 32 + lane];
        float x0 = Xs[(r0 + 0) * C_IN + k];
        float x1 = Xs[(r0 + 1) * C_IN + k];
        float x2 = Xs[(r0 + 2) * C_IN + k];
        float x3 = Xs[(r0 + 3) * C_IN + k];
        acc0.x += x0 * w.x; acc0.y += x0 * w.y; acc0.z += x0 * w.z; acc0.w += x0 * w.w;
        acc1.x += x1 * w.x; acc1.y += x1 * w.y; acc1.z += x1 * w.z; acc1.w += x1 * w.w;
        acc2.x += x2 * w.x; acc2.y += x2 * w.y; acc2.z += x2 * w.z; acc2.w += x2 * w.w;
        acc3.x += x3 * w.x; acc3.y += x3 * w.y; acc3.z += x3 * w.z; acc3.w += x3 * w.w;
    }

    float4 accs[4] = {acc0, acc1, acc2, acc3};
    #pragma unroll
    for (int r = 0; r < 4; r++) {
        int gr = rowBase + r0 + r;
        if (gr < n) ((float4*)g_H1)[(size_t)gr * 32 + lane] = accs[r];
    }
}

// ---------------------------------------------------------------------------
// Aggregation layer1: one warp per dst node, CSR edges, no atomics.
__global__ void __launch_bounds__(256) k_agg1(int n) {
    int w = (blockIdx.x * blockDim.x + threadIdx.x) >> 5;
    int lane = threadIdx.x & 31;
    if (w >= n) return;
    int d = w;
    float di = g_dis[d];
    float d2 = di * di;
    float4 acc = ((const float4*)g_H1)[(size_t)d * 32 + lane];
    acc.x *= d2; acc.y *= d2; acc.z *= d2; acc.w *= d2;

    int i = g_off[d], end = g_off[d + 1];
    for (; i + 2 <= end; i += 2) {
        int s0 = g_es[i], s1 = g_es[i + 1];
        float n0 = g_en[i], n1 = g_en[i + 1];
        float4 h0 = ((const float4*)g_H1)[(size_t)s0 * 32 + lane];
        float4 h1 = ((const float4*)g_H1)[(size_t)s1 * 32 + lane];
        acc.x += n0 * h0.x + n1 * h1.x;
        acc.y += n0 * h0.y + n1 * h1.y;
        acc.z += n0 * h0.z + n1 * h1.z;
        acc.w += n0 * h0.w + n1 * h1.w;
    }
    if (i < end) {
        int s0 = g_es[i];
        float n0 = g_en[i];
        float4 h0 = ((const float4*)g_H1)[(size_t)s0 * 32 + lane];
        acc.x += n0 * h0.x; acc.y += n0 * h0.y;
        acc.z += n0 * h0.z; acc.w += n0 * h0.w;
    }
    ((float4*)g_A1)[(size_t)d * 32 + lane] = acc;
}

// ---------------------------------------------------------------------------
// GEMM2: z = relu(A1 + b1); H2 = z @ W2
__global__ void __launch_bounds__(256) k_gemm2(
    const float* __restrict__ W2, const float* __restrict__ b1, int n)
{
    extern __shared__ float sm[];
    float2* Ws2 = (float2*)sm;                    // [128][32] float2 = 32KB
    float*  Xs  = sm + C_HID * C_OUT;             // [32][128] = 16KB

    int tid = threadIdx.x;
    const float2* Wg = (const float2*)W2;
    #pragma unroll
    for (int i = tid; i < (C_HID * C_OUT) / 2; i += 256) Ws2[i] = Wg[i];

    int rowBase = blockIdx.x * 32;
    float4* Xs4 = (float4*)Xs;
    for (int i = tid; i < 32 * (C_HID / 4); i += 256) {
        int r = i >> 5, c = i & 31;
        int gr = rowBase + r;
        float4 v = make_float4(0.f, 0.f, 0.f, 0.f);
        if (gr < n) {
            v = ((const float4*)g_A1)[(size_t)gr * 32 + c];
            v.x = fmaxf(v.x + __ldg(&b1[c * 4 + 0]), 0.f);
            v.y = fmaxf(v.y + __ldg(&b1[c * 4 + 1]), 0.f);
            v.z = fmaxf(v.z + __ldg(&b1[c * 4 + 2]), 0.f);
            v.w = fmaxf(v.w + __ldg(&b1[c * 4 + 3]), 0.f);
        }
        Xs4[i] = v;
    }
    __syncthreads();

    int warp = tid >> 5, lane = tid & 31;
    int r0 = warp * 4;
    float2 acc0 = {0,0}, acc1 = {0,0}, acc2 = {0,0}, acc3 = {0,0};

    #pragma unroll 4
    for (int k = 0; k < C_HID; k++) {
        float2 w = Ws2[k * 32 + lane];
        float x0 = Xs[(r0 + 0) * C_HID + k];
        float x1 = Xs[(r0 + 1) * C_HID + k];
        float x2 = Xs[(r0 + 2) * C_HID + k];
        float x3 = Xs[(r0 + 3) * C_HID + k];
        acc0.x += x0 * w.x; acc0.y += x0 * w.y;
        acc1.x += x1 * w.x; acc1.y += x1 * w.y;
        acc2.x += x2 * w.x; acc2.y += x2 * w.y;
        acc3.x += x3 * w.x; acc3.y += x3 * w.y;
    }

    float2 accs[4] = {acc0, acc1, acc2, acc3};
    #pragma unroll
    for (int r = 0; r < 4; r++) {
        int gr = rowBase + r0 + r;
        if (gr < n) ((float2*)g_H2)[(size_t)gr * 32 + lane] = accs[r];
    }
}

// ---------------------------------------------------------------------------
// Aggregation layer2: half-warp per dst node (64 cols = 16 lanes x float4).
__global__ void __launch_bounds__(256) k_agg2(
    const float* __restrict__ b2, float* __restrict__ out, int n)
{
    int hw = (blockIdx.x * blockDim.x + threadIdx.x) >> 4;
    int l16 = threadIdx.x & 15;
    if (hw >= n) return;
    int d = hw;
    float di = g_dis[d];
    float d2 = di * di;
    float4 acc = ((const float4*)g_H2)[(size_t)d * 16 + l16];
    acc.x *= d2; acc.y *= d2; acc.z *= d2; acc.w *= d2;

    int i = g_off[d], end = g_off[d + 1];
    for (; i + 2 <= end; i += 2) {
        int s0 = g_es[i], s1 = g_es[i + 1];
        float n0 = g_en[i], n1 = g_en[i + 1];
        float4 h0 = ((const float4*)g_H2)[(size_t)s0 * 16 + l16];
        float4 h1 = ((const float4*)g_H2)[(size_t)s1 * 16 + l16];
        acc.x += n0 * h0.x + n1 * h1.x;
        acc.y += n0 * h0.y + n1 * h1.y;
        acc.z += n0 * h0.z + n1 * h1.z;
        acc.w += n0 * h0.w + n1 * h1.w;
    }
    if (i < end) {
        int s0 = g_es[i];
        float n0 = g_en[i];
        float4 h0 = ((const float4*)g_H2)[(size_t)s0 * 16 + l16];
        acc.x += n0 * h0.x; acc.y += n0 * h0.y;
        acc.z += n0 * h0.z; acc.w += n0 * h0.w;
    }
    float4 bb = ((const float4*)b2)[l16];
    acc.x += bb.x; acc.y += bb.y; acc.z += bb.z; acc.w += bb.w;
    ((float4*)out)[(size_t)d * 16 + l16] = acc;
}

// ---------------------------------------------------------------------------
extern "C" void kernel_launch(void* const* d_in, const int* in_sizes, int n_in,
                              void* d_out, int out_size) {
    const float* x  = (const float*)d_in[0];
    const void*  ei = d_in[1];
    const float* W1 = (const float*)d_in[2];
    const float* b1 = (const float*)d_in[3];
    const float* W2 = (const float*)d_in[4];
    const float* b2 = (const float*)d_in[5];
    float* out = (float*)d_out;

    int n = in_sizes[0] / C_IN;        // 100000
    int E = in_sizes[1] / 2;           // 1600000

    cudaFuncSetAttribute(k_gemm1, cudaFuncAttributeMaxDynamicSharedMemorySize,
                         (C_IN * C_HID + 32 * C_IN) * sizeof(float));
    cudaFuncSetAttribute(k_gemm2, cudaFuncAttributeMaxDynamicSharedMemorySize,
                         (C_HID * C_OUT + 32 * C_HID) * sizeof(float));

    int nb_nodes = (n + 255) / 256;
    int nb_edges = (E + 255) / 256;
    int nb_scan  = (n + SCAN_BLK - 1) / SCAN_BLK;   // 391 for n=100000

    k_detect<<<1, 32>>>((const int*)ei);
    k_zero<<<nb_nodes, 256>>>(n);
    k_count<<<nb_edges, 256>>>(ei, E);
    k_scan1<<<nb_scan, SCAN_BLK>>>(n);
    k_scan2<<<1, 1024>>>(nb_scan, n);
    k_scan3<<<nb_scan, SCAN_BLK>>>(n);
    k_place<<<nb_edges, 256>>>(E);

    int gemm_blocks = (n + 31) / 32;
    size_t smem1 = (size_t)(C_IN * C_HID + 32 * C_IN) * sizeof(float);   // 80KB
    size_t smem2 = (size_t)(C_HID * C_OUT + 32 * C_HID) * sizeof(float); // 48KB

    k_gemm1<<<gemm_blocks, 256, smem1>>>(x, W1, n);

    long long t1 = (long long)n * 32;
    k_agg1<<<(int)((t1 + 255) / 256), 256>>>(n);

    k_gemm2<<<gemm_blocks, 256, smem2>>>(W2, b1, n);

    long long t2 = (long long)n * 16;
    k_agg2<<<(int)((t2 + 255) / 256), 256>>>(b2, out, n);
}